// round 1
// baseline (speedup 1.0000x reference)
#include <cuda_runtime.h>
#include <cuda_bf16.h>
#include <math.h>

#define N_NODES 1000000
#define HID 256
#define NGRAPH 8192

// ---------------- device scratch (no allocations allowed) ----------------
__device__ float    g_e[N_NODES];     // logits, then exp(logit - segmax)
__device__ int      g_b32[N_NODES];   // batch converted to int32
__device__ unsigned g_smax[NGRAPH];   // ordered-uint encoded segment max
__device__ float    g_ssum[NGRAPH];   // segment sum of exp
__device__ int      g_is64;           // 1 if batch is int64

// ---------------- dtype detection for batch ----------------
__global__ void k_detect(const unsigned* __restrict__ w) {
    // int64: odd words are high words == 0 (values in [0,8192)).
    // int32: these words are batch[2001..9001] which are in graphs >= ~16 (nonzero).
    g_is64 = (w[2001] == 0u && w[4001] == 0u && w[6001] == 0u && w[9001] == 0u) ? 1 : 0;
}

__global__ void k_convert(const void* __restrict__ batch) {
    int i = blockIdx.x * blockDim.x + threadIdx.x;
    if (i >= N_NODES) return;
    int v;
    if (g_is64) v = (int)((const long long*)batch)[i];
    else        v = ((const int*)batch)[i];
    g_b32[i] = v;
}

// ---------------- init: zero output + segment scratch ----------------
__global__ void k_init(float* __restrict__ out) {
    int i = blockIdx.x * blockDim.x + threadIdx.x;
    if (i < NGRAPH * HID) out[i] = 0.0f;
    if (i < NGRAPH) { g_smax[i] = 0u; g_ssum[i] = 0.0f; }
}

// ---------------- K1: logits = tanh(x@W1 + b1) @ W2 + b2 ----------------
// Block: 256 threads, 64 nodes. x tile [64][256] resident in smem.
// 4 column tiles of 64; W1 streamed in [64][64] chunks (padded to 68 floats/row).
// Per-thread 4x4 register tile. Thread layout: trow=tid>>4 (16), tcol=tid&15 (16).
#define SMEM_LOGITS ((64 * 256 + 64 * 68) * 4)

__global__ void __launch_bounds__(256) k_logits(
    const float* __restrict__ x,  const float* __restrict__ W1,
    const float* __restrict__ b1, const float* __restrict__ W2,
    const float* __restrict__ b2)
{
    extern __shared__ float sm[];
    float* xs = sm;               // [64][256]
    float* ws = sm + 64 * 256;    // [64][68]

    const int tid = threadIdx.x;
    const int n0  = blockIdx.x * 64;

    // Load x tile: each row (256 floats = 64 float4) by 64 threads.
    {
        const int q = tid & 63;
        for (int rr = tid >> 6; rr < 64; rr += 4) {
            const int n = n0 + rr;
            float4 v = make_float4(0.f, 0.f, 0.f, 0.f);
            if (n < N_NODES)
                v = *(const float4*)&x[(size_t)n * HID + q * 4];
            *(float4*)&xs[rr * HID + q * 4] = v;
        }
    }

    const int trow = tid >> 4;   // 0..15 -> nodes trow*4 .. +3
    const int tcol = tid & 15;   // 0..15 -> cols  tcol*4 .. +3 within col tile

    float lsum0 = 0.f, lsum1 = 0.f, lsum2 = 0.f, lsum3 = 0.f;

    for (int ct = 0; ct < 4; ct++) {
        float acc[4][4];
        #pragma unroll
        for (int i = 0; i < 4; i++)
            #pragma unroll
            for (int j = 0; j < 4; j++) acc[i][j] = 0.f;

        for (int kc = 0; kc < 4; kc++) {
            __syncthreads();
            // load W1 chunk: rows kc*64.., cols ct*64.. -> ws[64][68]
            {
                const int wq = tid & 15;
                for (int rr = tid >> 4; rr < 64; rr += 16)
                    *(float4*)&ws[rr * 68 + wq * 4] =
                        *(const float4*)&W1[(size_t)(kc * 64 + rr) * HID + ct * 64 + wq * 4];
            }
            __syncthreads();

            const float* xb = &xs[(trow * 4) * HID + kc * 64];
            #pragma unroll 8
            for (int kk = 0; kk < 64; kk += 4) {
                float4 xv0 = *(const float4*)&xb[0 * HID + kk];
                float4 xv1 = *(const float4*)&xb[1 * HID + kk];
                float4 xv2 = *(const float4*)&xb[2 * HID + kk];
                float4 xv3 = *(const float4*)&xb[3 * HID + kk];
                #pragma unroll
                for (int dk = 0; dk < 4; dk++) {
                    float4 wv = *(const float4*)&ws[(kk + dk) * 68 + tcol * 4];
                    float x0 = ((const float*)&xv0)[dk];
                    float x1 = ((const float*)&xv1)[dk];
                    float x2 = ((const float*)&xv2)[dk];
                    float x3 = ((const float*)&xv3)[dk];
                    acc[0][0] += x0 * wv.x; acc[0][1] += x0 * wv.y;
                    acc[0][2] += x0 * wv.z; acc[0][3] += x0 * wv.w;
                    acc[1][0] += x1 * wv.x; acc[1][1] += x1 * wv.y;
                    acc[1][2] += x1 * wv.z; acc[1][3] += x1 * wv.w;
                    acc[2][0] += x2 * wv.x; acc[2][1] += x2 * wv.y;
                    acc[2][2] += x2 * wv.z; acc[2][3] += x2 * wv.w;
                    acc[3][0] += x3 * wv.x; acc[3][1] += x3 * wv.y;
                    acc[3][2] += x3 * wv.z; acc[3][3] += x3 * wv.w;
                }
            }
        }

        // epilogue for this column tile: tanh + dot with W2
        const float4 b1v = *(const float4*)&b1[ct * 64 + tcol * 4];
        const float4 w2v = *(const float4*)&W2[ct * 64 + tcol * 4];
        const float bb[4] = {b1v.x, b1v.y, b1v.z, b1v.w};
        const float ww[4] = {w2v.x, w2v.y, w2v.z, w2v.w};
        float ls[4] = {0.f, 0.f, 0.f, 0.f};
        #pragma unroll
        for (int i = 0; i < 4; i++)
            #pragma unroll
            for (int j = 0; j < 4; j++)
                ls[i] += tanhf(acc[i][j] + bb[j]) * ww[j];
        lsum0 += ls[0]; lsum1 += ls[1]; lsum2 += ls[2]; lsum3 += ls[3];
    }

    // reduce across the 16 thread-columns (lane groups of 16)
    #pragma unroll
    for (int m = 8; m >= 1; m >>= 1) {
        lsum0 += __shfl_xor_sync(0xffffffffu, lsum0, m, 16);
        lsum1 += __shfl_xor_sync(0xffffffffu, lsum1, m, 16);
        lsum2 += __shfl_xor_sync(0xffffffffu, lsum2, m, 16);
        lsum3 += __shfl_xor_sync(0xffffffffu, lsum3, m, 16);
    }
    if (tcol == 0) {
        const float bb2 = b2[0];
        const int nb = n0 + trow * 4;
        if (nb + 0 < N_NODES) g_e[nb + 0] = lsum0 + bb2;
        if (nb + 1 < N_NODES) g_e[nb + 1] = lsum1 + bb2;
        if (nb + 2 < N_NODES) g_e[nb + 2] = lsum2 + bb2;
        if (nb + 3 < N_NODES) g_e[nb + 3] = lsum3 + bb2;
    }
}

// ---------------- K2: segment max (ordered-uint atomicMax) ----------------
__device__ __forceinline__ unsigned f2key(float f) {
    unsigned b = __float_as_uint(f);
    return (b & 0x80000000u) ? ~b : (b | 0x80000000u);
}
__device__ __forceinline__ float key2f(unsigned k) {
    return (k & 0x80000000u) ? __uint_as_float(k ^ 0x80000000u)
                             : __uint_as_float(~k);
}

__global__ void k_smax() {
    int i = blockIdx.x * blockDim.x + threadIdx.x;
    if (i >= N_NODES) return;
    atomicMax(&g_smax[g_b32[i]], f2key(g_e[i]));
}

// ---------------- K3: e = exp(l - max), segment sum ----------------
__global__ void k_esum() {
    int i = blockIdx.x * blockDim.x + threadIdx.x;
    if (i >= N_NODES) return;
    const int g = g_b32[i];
    const float m = key2f(g_smax[g]);
    const float e = expf(g_e[i] - m);
    g_e[i] = e;
    atomicAdd(&g_ssum[g], e);
}

// ---------------- K4: weighted segmented pooling ----------------
// Block: 128 nodes x 256 columns (thread t = column t). batch sorted ->
// run-length accumulate in a register, flush once per segment boundary.
__global__ void __launch_bounds__(256) k_pool(const float* __restrict__ x,
                                              float* __restrict__ out)
{
    __shared__ float wS[128];
    __shared__ int   bS[128];
    const int t  = threadIdx.x;
    const int n0 = blockIdx.x * 128;
    const int cnt = min(128, N_NODES - n0);

    if (t < 128) {
        if (t < cnt) {
            const int g = g_b32[n0 + t];
            bS[t] = g;
            wS[t] = g_e[n0 + t] / g_ssum[g];
        } else { bS[t] = -1; wS[t] = 0.f; }
    }
    __syncthreads();

    int   curg = bS[0];
    float acc  = 0.f;
    for (int i = 0; i < cnt; i++) {
        const int g = bS[i];
        if (g != curg) {
            atomicAdd(&out[(size_t)curg * HID + t], acc);
            acc = 0.f; curg = g;
        }
        acc += wS[i] * x[(size_t)(n0 + i) * HID + t];
    }
    atomicAdd(&out[(size_t)curg * HID + t], acc);
}

// ---------------- launcher ----------------
extern "C" void kernel_launch(void* const* d_in, const int* in_sizes, int n_in,
                              void* d_out, int out_size)
{
    const float* x = nullptr; const void* batch = nullptr;
    const float *W1 = nullptr, *b1 = nullptr, *W2 = nullptr, *b2 = nullptr;

    int i = 0;
    for (; i < n_in; i++) if (in_sizes[i] == N_NODES * HID) { x = (const float*)d_in[i]; i++; break; }
    for (; i < n_in; i++) if (in_sizes[i] == N_NODES)       { batch = d_in[i]; i++; break; }
    for (; i < n_in; i++) if (in_sizes[i] == HID * HID)     { W1 = (const float*)d_in[i]; i++; break; }
    for (; i < n_in; i++) if (in_sizes[i] == HID)           { b1 = (const float*)d_in[i]; i++; break; }
    for (; i < n_in; i++) if (in_sizes[i] == HID)           { W2 = (const float*)d_in[i]; i++; break; }
    for (; i < n_in; i++) if (in_sizes[i] == 1)             { b2 = (const float*)d_in[i]; i++; break; }
    if (!b2) { // fallback: last size-1 input
        for (int j = n_in - 1; j >= 0; j--) if (in_sizes[j] == 1) { b2 = (const float*)d_in[j]; break; }
    }
    if (!x || !batch || !W1 || !b1 || !W2 || !b2) return;

    float* out = (float*)d_out;

    cudaFuncSetAttribute(k_logits, cudaFuncAttributeMaxDynamicSharedMemorySize, SMEM_LOGITS);

    k_detect<<<1, 1>>>((const unsigned*)batch);

    {
        const int tot = NGRAPH * HID;
        k_init<<<(tot + 1023) / 1024, 1024>>>(out);
    }
    k_convert<<<(N_NODES + 1023) / 1024, 1024>>>(batch);

    k_logits<<<(N_NODES + 63) / 64, 256, SMEM_LOGITS>>>(x, W1, b1, W2, b2);

    k_smax<<<(N_NODES + 1023) / 1024, 1024>>>();
    k_esum<<<(N_NODES + 1023) / 1024, 1024>>>();

    k_pool<<<(N_NODES + 127) / 128, 256>>>(x, out);
}

// round 3
// speedup vs baseline: 2.8367x; 2.8367x over previous
#include <cuda_runtime.h>
#include <cuda_bf16.h>
#include <math.h>
#include <stdint.h>

#define N_NODES 1000000
#define HID 256
#define NGRAPH 8192
#define NTILES (N_NODES / 64)   // 15625, exact

// ---------------- device scratch ----------------
__device__ float    g_e[N_NODES];     // logit partials, then exp()
__device__ int      g_b32[N_NODES];
__device__ unsigned g_smax[NGRAPH];
__device__ float    g_ssum[NGRAPH];
__device__ int      g_is64;
// W1^T bf16 images [nh][hi/lo][128 rows x 512B], XOR-swizzled 16B chunks
__device__ __align__(16) unsigned char g_wimg[2][2][65536];

// ---------------- PTX helpers (base-target safe) ----------------
__device__ __forceinline__ uint32_t smem_u32(const void* p) {
    uint32_t a;
    asm("{ .reg .u64 t; cvta.to.shared.u64 t, %1; cvt.u32.u64 %0, t; }" : "=r"(a) : "l"(p));
    return a;
}
#define LDSM4(r, addr) \
    asm volatile("ldmatrix.sync.aligned.m8n8.x4.shared.b16 {%0,%1,%2,%3}, [%4];" \
        : "=r"((r)[0]), "=r"((r)[1]), "=r"((r)[2]), "=r"((r)[3]) : "r"(addr))
#define MMA16816(d, a, b0, b1) \
    asm volatile("mma.sync.aligned.m16n8k16.row.col.f32.bf16.bf16.f32 " \
        "{%0,%1,%2,%3}, {%4,%5,%6,%7}, {%8,%9}, {%0,%1,%2,%3};" \
        : "+f"((d)[0]), "+f"((d)[1]), "+f"((d)[2]), "+f"((d)[3]) \
        : "r"((a)[0]), "r"((a)[1]), "r"((a)[2]), "r"((a)[3]), "r"(b0), "r"(b1))

// ---------------- batch detect / convert ----------------
__global__ void k_detect(const unsigned* __restrict__ w) {
    g_is64 = (w[2001] == 0u && w[4001] == 0u && w[6001] == 0u && w[9001] == 0u) ? 1 : 0;
}
__global__ void k_convert(const void* __restrict__ batch) {
    int i = blockIdx.x * blockDim.x + threadIdx.x;
    if (i >= N_NODES) return;
    int v;
    if (g_is64) v = (int)((const long long*)batch)[i];
    else        v = ((const int*)batch)[i];
    g_b32[i] = v;
}

// ---------------- init ----------------
__global__ void k_init(float* __restrict__ out) {
    int i = blockIdx.x * blockDim.x + threadIdx.x;
    if (i < NGRAPH * HID) out[i] = 0.0f;
    if (i < N_NODES) g_e[i] = 0.0f;
    if (i < NGRAPH) { g_smax[i] = 0u; g_ssum[i] = 0.0f; }
}

// ---------------- W1 -> bf16 hi/lo swizzled images ----------------
// image row n (unit within half), 512B = 256 k * bf16; chunk kc=k/8, phys = kc ^ (n&7)
__global__ void k_prepw(const float* __restrict__ W1) {
    int i = blockIdx.x * blockDim.x + threadIdx.x;
    if (i >= HID * HID) return;
    int k = i >> 8, j = i & 255;           // W1[k][j]
    float w = W1[i];
    __nv_bfloat16 hb = __float2bfloat16(w);
    float r = w - __bfloat162float(hb);
    __nv_bfloat16 lb = __float2bfloat16(r);
    int nh = j >> 7, n = j & 127;
    int kc = k >> 3;
    uint32_t off = (uint32_t)(n * 512 + ((kc ^ (n & 7)) << 4) + (k & 7) * 2);
    *(__nv_bfloat16*)&g_wimg[nh][0][off] = hb;
    *(__nv_bfloat16*)&g_wimg[nh][1][off] = lb;
}

// ---------------- K1: HMMA GEMM + tanh + W2 dot ----------------
// smem: [Wh 64K][Wl 64K][Xh 32K][Xl 32K] = 192KB dynamic
#define S_WH 0
#define S_WL 65536
#define S_XH 131072
#define S_XL 163840
#define SMEM_K1 196608

__global__ void __launch_bounds__(256, 1) k_logits_mma(
    const float* __restrict__ x, const float* __restrict__ b1, const float* __restrict__ W2)
{
    extern __shared__ char sm_[];
    __shared__ float sacc[64];
    __shared__ float b1s[128], w2s[128];

    const int tid  = threadIdx.x;
    const int wid  = tid >> 5;
    const int lane = tid & 31;
    const int nh   = blockIdx.x & 1;
    const int wm   = wid & 1;       // m half (32 rows)
    const int wn   = wid >> 1;      // n group (32 units)

    // copy both W images (hi||lo contiguous, 128KB)
    {
        const uint4* gw = (const uint4*)&g_wimg[nh][0][0];
        uint4* dw = (uint4*)(sm_ + S_WH);
        for (int i2 = tid; i2 < 8192; i2 += 256) dw[i2] = gw[i2];
    }
    if (tid < 128) { b1s[tid] = b1[nh * 128 + tid]; w2s[tid] = W2[nh * 128 + tid]; }

    const uint32_t sb = smem_u32(sm_);
    const uint32_t xh = sb + S_XH, xl = sb + S_XL;
    const uint32_t wh = sb + S_WH, wl = sb + S_WL;

    // ldmatrix per-lane address precompute
    const int rowA0 = wm * 32 +  0 + (lane & 15);
    const int rowA1 = wm * 32 + 16 + (lane & 15);
    const uint32_t aoff0 = rowA0 * 512; const int a70 = rowA0 & 7;
    const uint32_t aoff1 = rowA1 * 512; const int a71 = rowA1 & 7;
    const int acs = (lane >> 4) & 1;

    const int rowB0 = wn * 32 +  0 + (lane & 7) + (((lane >> 4) & 1) << 3);
    const int rowB1 = wn * 32 + 16 + (lane & 7) + (((lane >> 4) & 1) << 3);
    const uint32_t boff0 = rowB0 * 512; const int b70 = rowB0 & 7;
    const uint32_t boff1 = rowB1 * 512; const int b71 = rowB1 & 7;
    const int bcs = (lane >> 3) & 1;

    const int step = (int)(gridDim.x >> 1);

    for (int tI = blockIdx.x >> 1; tI < NTILES; tI += step) {
        __syncthreads();   // prev tile fully consumed
        const int node0 = tI * 64;

        // ---- load x tile, split to bf16 hi/lo, store swizzled ----
        #pragma unroll
        for (int i2 = 0; i2 < 8; i2++) {
            const int c   = i2 * 256 + tid;   // 16B-chunk id
            const int row = c >> 5;
            const int kc  = c & 31;
            const float4* gp = (const float4*)(x + (size_t)(node0 + row) * HID + kc * 8);
            const float4 f0 = __ldg(gp);
            const float4 f1 = __ldg(gp + 1);
            __nv_bfloat162 h0 = __floats2bfloat162_rn(f0.x, f0.y);
            __nv_bfloat162 h1 = __floats2bfloat162_rn(f0.z, f0.w);
            __nv_bfloat162 h2 = __floats2bfloat162_rn(f1.x, f1.y);
            __nv_bfloat162 h3 = __floats2bfloat162_rn(f1.z, f1.w);
            __nv_bfloat162 l0 = __floats2bfloat162_rn(f0.x - __low2float(h0), f0.y - __high2float(h0));
            __nv_bfloat162 l1 = __floats2bfloat162_rn(f0.z - __low2float(h1), f0.w - __high2float(h1));
            __nv_bfloat162 l2 = __floats2bfloat162_rn(f1.x - __low2float(h2), f1.y - __high2float(h2));
            __nv_bfloat162 l3 = __floats2bfloat162_rn(f1.z - __low2float(h3), f1.w - __high2float(h3));
            uint4 uh, ul;
            uh.x = *(uint32_t*)&h0; uh.y = *(uint32_t*)&h1;
            uh.z = *(uint32_t*)&h2; uh.w = *(uint32_t*)&h3;
            ul.x = *(uint32_t*)&l0; ul.y = *(uint32_t*)&l1;
            ul.z = *(uint32_t*)&l2; ul.w = *(uint32_t*)&l3;
            const uint32_t ad = (row << 9) + (((kc ^ (row & 7))) << 4);
            *(uint4*)(sm_ + S_XH + ad) = uh;
            *(uint4*)(sm_ + S_XL + ad) = ul;
        }
        if (tid < 64) sacc[tid] = 0.f;
        __syncthreads();

        // ---- GEMM: D = Xh*Wh + Xl*Wh + Xh*Wl ----
        float d[2][4][4];
        #pragma unroll
        for (int mi = 0; mi < 2; mi++)
            #pragma unroll
            for (int nt = 0; nt < 4; nt++)
                #pragma unroll
                for (int q = 0; q < 4; q++) d[mi][nt][q] = 0.f;

        #pragma unroll 4
        for (int ks = 0; ks < 16; ks++) {
            const uint32_t ao0 = aoff0 + ((((ks << 1) + acs) ^ a70) << 4);
            const uint32_t ao1 = aoff1 + ((((ks << 1) + acs) ^ a71) << 4);
            const uint32_t bo0 = boff0 + ((((ks << 1) + bcs) ^ b70) << 4);
            const uint32_t bo1 = boff1 + ((((ks << 1) + bcs) ^ b71) << 4);
            uint32_t Ah0[4], Ah1[4], Al0[4], Al1[4];
            uint32_t Bh0[4], Bh1[4], Bl0[4], Bl1[4];
            LDSM4(Ah0, xh + ao0); LDSM4(Ah1, xh + ao1);
            LDSM4(Al0, xl + ao0); LDSM4(Al1, xl + ao1);
            LDSM4(Bh0, wh + bo0); LDSM4(Bh1, wh + bo1);
            LDSM4(Bl0, wl + bo0); LDSM4(Bl1, wl + bo1);

            MMA16816(d[0][0], Ah0, Bh0[0], Bh0[1]);
            MMA16816(d[0][1], Ah0, Bh0[2], Bh0[3]);
            MMA16816(d[0][2], Ah0, Bh1[0], Bh1[1]);
            MMA16816(d[0][3], Ah0, Bh1[2], Bh1[3]);
            MMA16816(d[1][0], Ah1, Bh0[0], Bh0[1]);
            MMA16816(d[1][1], Ah1, Bh0[2], Bh0[3]);
            MMA16816(d[1][2], Ah1, Bh1[0], Bh1[1]);
            MMA16816(d[1][3], Ah1, Bh1[2], Bh1[3]);

            MMA16816(d[0][0], Al0, Bh0[0], Bh0[1]);
            MMA16816(d[0][1], Al0, Bh0[2], Bh0[3]);
            MMA16816(d[0][2], Al0, Bh1[0], Bh1[1]);
            MMA16816(d[0][3], Al0, Bh1[2], Bh1[3]);
            MMA16816(d[1][0], Al1, Bh0[0], Bh0[1]);
            MMA16816(d[1][1], Al1, Bh0[2], Bh0[3]);
            MMA16816(d[1][2], Al1, Bh1[0], Bh1[1]);
            MMA16816(d[1][3], Al1, Bh1[2], Bh1[3]);

            MMA16816(d[0][0], Ah0, Bl0[0], Bl0[1]);
            MMA16816(d[0][1], Ah0, Bl0[2], Bl0[3]);
            MMA16816(d[0][2], Ah0, Bl1[0], Bl1[1]);
            MMA16816(d[0][3], Ah0, Bl1[2], Bl1[3]);
            MMA16816(d[1][0], Ah1, Bl0[0], Bl0[1]);
            MMA16816(d[1][1], Ah1, Bl0[2], Bl0[3]);
            MMA16816(d[1][2], Ah1, Bl1[0], Bl1[1]);
            MMA16816(d[1][3], Ah1, Bl1[2], Bl1[3]);
        }

        // ---- epilogue: tanh(+b1) dot W2, reduce, accumulate ----
        const int qid = lane & 3;
        const int rq  = lane >> 2;
        #pragma unroll
        for (int mi = 0; mi < 2; mi++) {
            float s0 = 0.f, s1 = 0.f;
            #pragma unroll
            for (int nt = 0; nt < 4; nt++) {
                const int c0 = wn * 32 + nt * 8 + qid * 2;
                const float bb0 = b1s[c0], bb1 = b1s[c0 + 1];
                const float ww0 = w2s[c0], ww1 = w2s[c0 + 1];
                s0 += tanhf(d[mi][nt][0] + bb0) * ww0 + tanhf(d[mi][nt][1] + bb1) * ww1;
                s1 += tanhf(d[mi][nt][2] + bb0) * ww0 + tanhf(d[mi][nt][3] + bb1) * ww1;
            }
            s0 += __shfl_xor_sync(0xffffffffu, s0, 1);
            s0 += __shfl_xor_sync(0xffffffffu, s0, 2);
            s1 += __shfl_xor_sync(0xffffffffu, s1, 1);
            s1 += __shfl_xor_sync(0xffffffffu, s1, 2);
            if (qid == 0) {
                atomicAdd(&sacc[wm * 32 + mi * 16 + rq], s0);
                atomicAdd(&sacc[wm * 32 + mi * 16 + 8 + rq], s1);
            }
        }
        __syncthreads();
        if (tid < 64) atomicAdd(&g_e[node0 + tid], sacc[tid]);
    }
}

// ---------------- segment softmax passes ----------------
__device__ __forceinline__ unsigned f2key(float f) {
    unsigned b = __float_as_uint(f);
    return (b & 0x80000000u) ? ~b : (b | 0x80000000u);
}
__device__ __forceinline__ float key2f(unsigned k) {
    return (k & 0x80000000u) ? __uint_as_float(k ^ 0x80000000u) : __uint_as_float(~k);
}
__global__ void k_smax() {
    int i = blockIdx.x * blockDim.x + threadIdx.x;
    if (i >= N_NODES) return;
    atomicMax(&g_smax[g_b32[i]], f2key(g_e[i]));
}
__global__ void k_esum() {
    int i = blockIdx.x * blockDim.x + threadIdx.x;
    if (i >= N_NODES) return;
    const int g = g_b32[i];
    const float e = expf(g_e[i] - key2f(g_smax[g]));
    g_e[i] = e;
    atomicAdd(&g_ssum[g], e);
}

// ---------------- weighted segmented pooling ----------------
__global__ void __launch_bounds__(256) k_pool(const float* __restrict__ x,
                                              float* __restrict__ out)
{
    __shared__ float wS[128];
    __shared__ int   bS[128];
    const int t  = threadIdx.x;
    const int n0 = blockIdx.x * 128;
    const int cnt = min(128, N_NODES - n0);

    if (t < 128) {
        if (t < cnt) {
            const int g = g_b32[n0 + t];
            bS[t] = g;
            wS[t] = g_e[n0 + t] / g_ssum[g];
        } else { bS[t] = -1; wS[t] = 0.f; }
    }
    __syncthreads();

    int   curg = bS[0];
    float acc  = 0.f;
    for (int i = 0; i < cnt; i++) {
        const int g = bS[i];
        if (g != curg) {
            atomicAdd(&out[(size_t)curg * HID + t], acc);
            acc = 0.f; curg = g;
        }
        acc += wS[i] * x[(size_t)(n0 + i) * HID + t];
    }
    atomicAdd(&out[(size_t)curg * HID + t], acc);
}

// ---------------- launcher ----------------
extern "C" void kernel_launch(void* const* d_in, const int* in_sizes, int n_in,
                              void* d_out, int out_size)
{
    const float* x = nullptr; const void* batch = nullptr;
    const float *W1 = nullptr, *b1 = nullptr, *W2 = nullptr;

    int i = 0;
    for (; i < n_in; i++) if (in_sizes[i] == N_NODES * HID) { x = (const float*)d_in[i]; i++; break; }
    for (; i < n_in; i++) if (in_sizes[i] == N_NODES)       { batch = d_in[i]; i++; break; }
    for (; i < n_in; i++) if (in_sizes[i] == HID * HID)     { W1 = (const float*)d_in[i]; i++; break; }
    for (; i < n_in; i++) if (in_sizes[i] == HID)           { b1 = (const float*)d_in[i]; i++; break; }
    for (; i < n_in; i++) if (in_sizes[i] == HID)           { W2 = (const float*)d_in[i]; i++; break; }
    // b2 is dropped: softmax is shift-invariant
    if (!x || !batch || !W1 || !b1 || !W2) return;

    float* out = (float*)d_out;

    static int nsm = 0;
    if (nsm == 0) {
        if (cudaDeviceGetAttribute(&nsm, cudaDevAttrMultiProcessorCount, 0) != cudaSuccess || nsm <= 0)
            nsm = 148;
    }
    const int grid_k1 = nsm & ~1;

    cudaFuncSetAttribute(k_logits_mma, cudaFuncAttributeMaxDynamicSharedMemorySize, SMEM_K1);

    k_detect<<<1, 1>>>((const unsigned*)batch);
    k_init<<<(NGRAPH * HID + 1023) / 1024, 1024>>>(out);
    k_convert<<<(N_NODES + 1023) / 1024, 1024>>>(batch);
    k_prepw<<<(HID * HID + 255) / 256, 256>>>(W1);

    k_logits_mma<<<grid_k1, 256, SMEM_K1>>>(x, b1, W2);

    k_smax<<<(N_NODES + 1023) / 1024, 1024>>>();
    k_esum<<<(N_NODES + 1023) / 1024, 1024>>>();
    k_pool<<<(N_NODES + 127) / 128, 256>>>(x, out);
}

// round 4
// speedup vs baseline: 3.1309x; 1.1037x over previous
#include <cuda_runtime.h>
#include <cuda_bf16.h>
#include <math.h>
#include <stdint.h>

#define N_NODES 1000000
#define HID 256
#define NGRAPH 8192
#define NTILES (N_NODES / 64)   // 15625, exact

// ---------------- device scratch ----------------
__device__ float    g_e[N_NODES];     // logit partials -> exp()
__device__ int      g_b32[N_NODES];
// W1^T bf16 images [nh][hi/lo][128 rows x 512B], XOR-swizzled 16B chunks
__device__ __align__(16) unsigned char g_wimg[2][2][65536];

// ---------------- PTX helpers (base-target safe) ----------------
__device__ __forceinline__ uint32_t smem_u32(const void* p) {
    uint32_t a;
    asm("{ .reg .u64 t; cvta.to.shared.u64 t, %1; cvt.u32.u64 %0, t; }" : "=r"(a) : "l"(p));
    return a;
}
#define LDSM4(r, addr) \
    asm volatile("ldmatrix.sync.aligned.m8n8.x4.shared.b16 {%0,%1,%2,%3}, [%4];" \
        : "=r"((r)[0]), "=r"((r)[1]), "=r"((r)[2]), "=r"((r)[3]) : "r"(addr))
#define MMA16816(d, a, b0, b1) \
    asm volatile("mma.sync.aligned.m16n8k16.row.col.f32.bf16.bf16.f32 " \
        "{%0,%1,%2,%3}, {%4,%5,%6,%7}, {%8,%9}, {%0,%1,%2,%3};" \
        : "+f"((d)[0]), "+f"((d)[1]), "+f"((d)[2]), "+f"((d)[3]) \
        : "r"((a)[0]), "r"((a)[1]), "r"((a)[2]), "r"((a)[3]), "r"(b0), "r"(b1))

// ---------------- fused prep: detect + convert + zero + W images ----------------
__global__ void k_prep(const float* __restrict__ W1, const void* __restrict__ batch) {
    const int i = blockIdx.x * blockDim.x + threadIdx.x;
    // inline dtype detection (uniform loads, L1 broadcast)
    const unsigned* wv = (const unsigned*)batch;
    const bool is64 = (wv[2001] == 0u && wv[4001] == 0u && wv[6001] == 0u && wv[9001] == 0u);
    if (i < N_NODES) {
        g_e[i] = 0.0f;
        g_b32[i] = is64 ? (int)((const long long*)batch)[i] : ((const int*)batch)[i];
    }
    if (i < HID * HID) {
        const int k = i >> 8, j = i & 255;          // W1[k][j]
        const float w = W1[i];
        const __nv_bfloat16 hb = __float2bfloat16(w);
        const float r = w - __bfloat162float(hb);
        const __nv_bfloat16 lb = __float2bfloat16(r);
        const int nh = j >> 7, n = j & 127;
        const int kc = k >> 3;
        const uint32_t off = (uint32_t)(n * 512 + ((kc ^ (n & 7)) << 4) + (k & 7) * 2);
        *(__nv_bfloat16*)&g_wimg[nh][0][off] = hb;
        *(__nv_bfloat16*)&g_wimg[nh][1][off] = lb;
    }
}

// ---------------- K1: HMMA GEMM + tanh + W2 dot (prefetch pipelined) ----------------
#define S_WH 0
#define S_WL 65536
#define S_XH 131072
#define S_XL 163840
#define SMEM_K1 196608

__global__ void __launch_bounds__(256, 1) k_logits_mma(
    const float* __restrict__ x, const float* __restrict__ b1, const float* __restrict__ W2)
{
    extern __shared__ char sm_[];
    __shared__ float sacc[64];
    __shared__ float b1s[128], w2s[128];

    const int tid  = threadIdx.x;
    const int wid  = tid >> 5;
    const int lane = tid & 31;
    const int nh   = blockIdx.x & 1;
    const int wm   = wid & 1;       // m half (32 rows)
    const int wn   = wid >> 1;      // n group (32 units)

    // copy W images (hi||lo, 128KB)
    {
        const uint4* gw = (const uint4*)&g_wimg[nh][0][0];
        uint4* dw = (uint4*)(sm_ + S_WH);
        for (int i2 = tid; i2 < 8192; i2 += 256) dw[i2] = gw[i2];
    }
    if (tid < 128) { b1s[tid] = b1[nh * 128 + tid]; w2s[tid] = W2[nh * 128 + tid]; }

    const uint32_t sb = smem_u32(sm_);
    const uint32_t xh = sb + S_XH, xl = sb + S_XL;
    const uint32_t wh = sb + S_WH, wl = sb + S_WL;

    // per-thread global/shared address components (tile-invariant)
    int rowc[8], kcc[8];
    #pragma unroll
    for (int i2 = 0; i2 < 8; i2++) {
        const int c = i2 * 256 + tid;
        rowc[i2] = c >> 5;
        kcc[i2]  = c & 31;
    }

    // ldmatrix per-lane address precompute
    const int rowA0 = wm * 32 +  0 + (lane & 15);
    const int rowA1 = wm * 32 + 16 + (lane & 15);
    const uint32_t aoff0 = rowA0 * 512; const int a70 = rowA0 & 7;
    const uint32_t aoff1 = rowA1 * 512; const int a71 = rowA1 & 7;
    const int acs = (lane >> 4) & 1;

    const int rowB0 = wn * 32 +  0 + (lane & 7) + (((lane >> 4) & 1) << 3);
    const int rowB1 = wn * 32 + 16 + (lane & 7) + (((lane >> 4) & 1) << 3);
    const uint32_t boff0 = rowB0 * 512; const int b70 = rowB0 & 7;
    const uint32_t boff1 = rowB1 * 512; const int b71 = rowB1 & 7;
    const int bcs = (lane >> 3) & 1;

    const int step = (int)(gridDim.x >> 1);

    // ---- prologue: prefetch first tile into registers ----
    float4 pf0[8], pf1[8];
    int t = blockIdx.x >> 1;
    if (t < NTILES) {
        const int node0 = t * 64;
        #pragma unroll
        for (int i2 = 0; i2 < 8; i2++) {
            const float4* gp = (const float4*)(x + (size_t)(node0 + rowc[i2]) * HID + kcc[i2] * 8);
            pf0[i2] = __ldg(gp);
            pf1[i2] = __ldg(gp + 1);
        }
    }

    for (; t < NTILES; t += step) {
        __syncthreads();   // prev tile fully consumed

        // ---- convert prefetched tile -> bf16 hi/lo swizzled smem ----
        #pragma unroll
        for (int i2 = 0; i2 < 8; i2++) {
            const float4 f0 = pf0[i2], f1 = pf1[i2];
            __nv_bfloat162 h0 = __floats2bfloat162_rn(f0.x, f0.y);
            __nv_bfloat162 h1 = __floats2bfloat162_rn(f0.z, f0.w);
            __nv_bfloat162 h2 = __floats2bfloat162_rn(f1.x, f1.y);
            __nv_bfloat162 h3 = __floats2bfloat162_rn(f1.z, f1.w);
            __nv_bfloat162 l0 = __floats2bfloat162_rn(f0.x - __low2float(h0), f0.y - __high2float(h0));
            __nv_bfloat162 l1 = __floats2bfloat162_rn(f0.z - __low2float(h1), f0.w - __high2float(h1));
            __nv_bfloat162 l2 = __floats2bfloat162_rn(f1.x - __low2float(h2), f1.y - __high2float(h2));
            __nv_bfloat162 l3 = __floats2bfloat162_rn(f1.z - __low2float(h3), f1.w - __high2float(h3));
            uint4 uh, ul;
            uh.x = *(uint32_t*)&h0; uh.y = *(uint32_t*)&h1;
            uh.z = *(uint32_t*)&h2; uh.w = *(uint32_t*)&h3;
            ul.x = *(uint32_t*)&l0; ul.y = *(uint32_t*)&l1;
            ul.z = *(uint32_t*)&l2; ul.w = *(uint32_t*)&l3;
            const uint32_t ad = (rowc[i2] << 9) + ((kcc[i2] ^ (rowc[i2] & 7)) << 4);
            *(uint4*)(sm_ + S_XH + ad) = uh;
            *(uint4*)(sm_ + S_XL + ad) = ul;
        }
        if (tid < 64) sacc[tid] = 0.f;
        __syncthreads();

        // ---- prefetch next tile (latency hides under MMA below) ----
        {
            const int tn = t + step;
            if (tn < NTILES) {
                const int node0n = tn * 64;
                #pragma unroll
                for (int i2 = 0; i2 < 8; i2++) {
                    const float4* gp = (const float4*)(x + (size_t)(node0n + rowc[i2]) * HID + kcc[i2] * 8);
                    pf0[i2] = __ldg(gp);
                    pf1[i2] = __ldg(gp + 1);
                }
            }
        }

        // ---- GEMM: D = Xh*Wh + Xl*Wh + Xh*Wl ----
        float d[2][4][4];
        #pragma unroll
        for (int mi = 0; mi < 2; mi++)
            #pragma unroll
            for (int nt = 0; nt < 4; nt++)
                #pragma unroll
                for (int q = 0; q < 4; q++) d[mi][nt][q] = 0.f;

        #pragma unroll 4
        for (int ks = 0; ks < 16; ks++) {
            const uint32_t ao0 = aoff0 + ((((ks << 1) + acs) ^ a70) << 4);
            const uint32_t ao1 = aoff1 + ((((ks << 1) + acs) ^ a71) << 4);
            const uint32_t bo0 = boff0 + ((((ks << 1) + bcs) ^ b70) << 4);
            const uint32_t bo1 = boff1 + ((((ks << 1) + bcs) ^ b71) << 4);
            uint32_t Ah0[4], Ah1[4], Al0[4], Al1[4];
            uint32_t Bh0[4], Bh1[4], Bl0[4], Bl1[4];
            LDSM4(Ah0, xh + ao0); LDSM4(Ah1, xh + ao1);
            LDSM4(Al0, xl + ao0); LDSM4(Al1, xl + ao1);
            LDSM4(Bh0, wh + bo0); LDSM4(Bh1, wh + bo1);
            LDSM4(Bl0, wl + bo0); LDSM4(Bl1, wl + bo1);

            MMA16816(d[0][0], Ah0, Bh0[0], Bh0[1]);
            MMA16816(d[0][1], Ah0, Bh0[2], Bh0[3]);
            MMA16816(d[0][2], Ah0, Bh1[0], Bh1[1]);
            MMA16816(d[0][3], Ah0, Bh1[2], Bh1[3]);
            MMA16816(d[1][0], Ah1, Bh0[0], Bh0[1]);
            MMA16816(d[1][1], Ah1, Bh0[2], Bh0[3]);
            MMA16816(d[1][2], Ah1, Bh1[0], Bh1[1]);
            MMA16816(d[1][3], Ah1, Bh1[2], Bh1[3]);

            MMA16816(d[0][0], Al0, Bh0[0], Bh0[1]);
            MMA16816(d[0][1], Al0, Bh0[2], Bh0[3]);
            MMA16816(d[0][2], Al0, Bh1[0], Bh1[1]);
            MMA16816(d[0][3], Al0, Bh1[2], Bh1[3]);
            MMA16816(d[1][0], Al1, Bh0[0], Bh0[1]);
            MMA16816(d[1][1], Al1, Bh0[2], Bh0[3]);
            MMA16816(d[1][2], Al1, Bh1[0], Bh1[1]);
            MMA16816(d[1][3], Al1, Bh1[2], Bh1[3]);

            MMA16816(d[0][0], Ah0, Bl0[0], Bl0[1]);
            MMA16816(d[0][1], Ah0, Bl0[2], Bl0[3]);
            MMA16816(d[0][2], Ah0, Bl1[0], Bl1[1]);
            MMA16816(d[0][3], Ah0, Bl1[2], Bl1[3]);
            MMA16816(d[1][0], Ah1, Bl0[0], Bl0[1]);
            MMA16816(d[1][1], Ah1, Bl0[2], Bl0[3]);
            MMA16816(d[1][2], Ah1, Bl1[0], Bl1[1]);
            MMA16816(d[1][3], Ah1, Bl1[2], Bl1[3]);
        }

        // ---- epilogue: tanh(+b1) dot W2, reduce, accumulate ----
        const int qid = lane & 3;
        const int rq  = lane >> 2;
        #pragma unroll
        for (int mi = 0; mi < 2; mi++) {
            float s0 = 0.f, s1 = 0.f;
            #pragma unroll
            for (int nt = 0; nt < 4; nt++) {
                const int c0 = wn * 32 + nt * 8 + qid * 2;
                const float bb0 = b1s[c0], bb1 = b1s[c0 + 1];
                const float ww0 = w2s[c0], ww1 = w2s[c0 + 1];
                s0 += tanhf(d[mi][nt][0] + bb0) * ww0 + tanhf(d[mi][nt][1] + bb1) * ww1;
                s1 += tanhf(d[mi][nt][2] + bb0) * ww0 + tanhf(d[mi][nt][3] + bb1) * ww1;
            }
            s0 += __shfl_xor_sync(0xffffffffu, s0, 1);
            s0 += __shfl_xor_sync(0xffffffffu, s0, 2);
            s1 += __shfl_xor_sync(0xffffffffu, s1, 1);
            s1 += __shfl_xor_sync(0xffffffffu, s1, 2);
            if (qid == 0) {
                atomicAdd(&sacc[wm * 32 + mi * 16 + rq], s0);
                atomicAdd(&sacc[wm * 32 + mi * 16 + 8 + rq], s1);
            }
        }
        __syncthreads();
        if (tid < 64) atomicAdd(&g_e[t * 64 + tid], sacc[tid]);
    }
}

// ---------------- k_seg: per-graph softmax + pooling (no atomics) ----------------
__global__ void __launch_bounds__(256) k_seg(const float* __restrict__ x,
                                             float* __restrict__ out)
{
    const int g   = blockIdx.x;
    const int tid = threadIdx.x;
    __shared__ float red[8];
    __shared__ float s_bcast;

    // binary search graph range in sorted g_b32 (uniform -> L1 broadcast)
    int lo = 0, hi = N_NODES;
    while (lo < hi) { int mid = (lo + hi) >> 1; if (g_b32[mid] < g) lo = mid + 1; else hi = mid; }
    const int beg = lo;
    lo = beg; hi = N_NODES;
    while (lo < hi) { int mid = (lo + hi) >> 1; if (g_b32[mid] < g + 1) lo = mid + 1; else hi = mid; }
    const int end = lo;

    if (end <= beg) { out[(size_t)g * HID + tid] = 0.0f; return; }

    // pass 1: max
    float m = -1e30f;
    for (int n = beg + tid; n < end; n += 256) m = fmaxf(m, g_e[n]);
    #pragma unroll
    for (int o = 16; o >= 1; o >>= 1) m = fmaxf(m, __shfl_xor_sync(0xffffffffu, m, o));
    if ((tid & 31) == 0) red[tid >> 5] = m;
    __syncthreads();
    if (tid < 8) {
        m = red[tid];
        #pragma unroll
        for (int o = 4; o >= 1; o >>= 1) m = fmaxf(m, __shfl_xor_sync(0xffu, m, o));
        if (tid == 0) s_bcast = m;
    }
    __syncthreads();
    const float mx = s_bcast;
    __syncthreads();

    // pass 2: exp + sum (store e back to g_e)
    float s = 0.f;
    for (int n = beg + tid; n < end; n += 256) {
        const float e = expf(g_e[n] - mx);
        g_e[n] = e;
        s += e;
    }
    #pragma unroll
    for (int o = 16; o >= 1; o >>= 1) s += __shfl_xor_sync(0xffffffffu, s, o);
    if ((tid & 31) == 0) red[tid >> 5] = s;
    __syncthreads();
    if (tid < 8) {
        s = red[tid];
        #pragma unroll
        for (int o = 4; o >= 1; o >>= 1) s += __shfl_xor_sync(0xffu, s, o);
        if (tid == 0) s_bcast = s;
    }
    __syncthreads();
    const float inv = 1.0f / s_bcast;

    // pooling: thread = column; e[n] is a uniform (broadcast) load
    float a0 = 0.f, a1 = 0.f, a2 = 0.f, a3 = 0.f;
    int n = beg;
    for (; n + 3 < end; n += 4) {
        a0 += g_e[n + 0] * x[(size_t)(n + 0) * HID + tid];
        a1 += g_e[n + 1] * x[(size_t)(n + 1) * HID + tid];
        a2 += g_e[n + 2] * x[(size_t)(n + 2) * HID + tid];
        a3 += g_e[n + 3] * x[(size_t)(n + 3) * HID + tid];
    }
    for (; n < end; n++) a0 += g_e[n] * x[(size_t)n * HID + tid];
    out[(size_t)g * HID + tid] = (a0 + a1 + a2 + a3) * inv;
}

// ---------------- launcher ----------------
extern "C" void kernel_launch(void* const* d_in, const int* in_sizes, int n_in,
                              void* d_out, int out_size)
{
    const float* x = nullptr; const void* batch = nullptr;
    const float *W1 = nullptr, *b1 = nullptr, *W2 = nullptr;

    int i = 0;
    for (; i < n_in; i++) if (in_sizes[i] == N_NODES * HID) { x = (const float*)d_in[i]; i++; break; }
    for (; i < n_in; i++) if (in_sizes[i] == N_NODES)       { batch = d_in[i]; i++; break; }
    for (; i < n_in; i++) if (in_sizes[i] == HID * HID)     { W1 = (const float*)d_in[i]; i++; break; }
    for (; i < n_in; i++) if (in_sizes[i] == HID)           { b1 = (const float*)d_in[i]; i++; break; }
    for (; i < n_in; i++) if (in_sizes[i] == HID)           { W2 = (const float*)d_in[i]; i++; break; }
    // b2 dropped: softmax is shift-invariant
    if (!x || !batch || !W1 || !b1 || !W2) return;

    float* out = (float*)d_out;

    static int nsm = 0;
    if (nsm == 0) {
        if (cudaDeviceGetAttribute(&nsm, cudaDevAttrMultiProcessorCount, 0) != cudaSuccess || nsm <= 0)
            nsm = 148;
    }
    const int grid_k1 = nsm & ~1;

    cudaFuncSetAttribute(k_logits_mma, cudaFuncAttributeMaxDynamicSharedMemorySize, SMEM_K1);

    k_prep<<<(N_NODES + 255) / 256, 256>>>(W1, batch);
    k_logits_mma<<<grid_k1, 256, SMEM_K1>>>(x, b1, W2);
    k_seg<<<NGRAPH, 256>>>(x, out);
}

// round 5
// speedup vs baseline: 4.3892x; 1.4019x over previous
#include <cuda_runtime.h>
#include <cuda_fp16.h>
#include <math.h>
#include <stdint.h>

#define N_NODES 1000000
#define HID 256
#define NGRAPH 8192
#define NTILES (N_NODES / 32)   // 31250, exact

// ---------------- device scratch ----------------
__device__ float g_e[N_NODES];     // logits -> exp()
__device__ int   g_b32[N_NODES];
// W1^T fp16 image: 256 units x 512B rows, XOR-swizzled 16B chunks
__device__ __align__(16) unsigned char g_wimg[131072];

// ---------------- PTX helpers ----------------
__device__ __forceinline__ uint32_t smem_u32(const void* p) {
    uint32_t a;
    asm("{ .reg .u64 t; cvta.to.shared.u64 t, %1; cvt.u32.u64 %0, t; }" : "=r"(a) : "l"(p));
    return a;
}
#define LDSM4(r, addr) \
    asm volatile("ldmatrix.sync.aligned.m8n8.x4.shared.b16 {%0,%1,%2,%3}, [%4];" \
        : "=r"((r)[0]), "=r"((r)[1]), "=r"((r)[2]), "=r"((r)[3]) : "r"(addr))
#define MMA16816(d, a, b0, b1) \
    asm volatile("mma.sync.aligned.m16n8k16.row.col.f32.f16.f16.f32 " \
        "{%0,%1,%2,%3}, {%4,%5,%6,%7}, {%8,%9}, {%0,%1,%2,%3};" \
        : "+f"((d)[0]), "+f"((d)[1]), "+f"((d)[2]), "+f"((d)[3]) \
        : "r"((a)[0]), "r"((a)[1]), "r"((a)[2]), "r"((a)[3]), "r"(b0), "r"(b1))

// ---------------- nop kernels (ncu launch-slot alignment) ----------------
__global__ void k_nop() {}

// ---------------- prep: batch convert + W fp16 swizzled image ----------------
__global__ void k_prep(const float* __restrict__ W1, const void* __restrict__ batch) {
    const int i = blockIdx.x * blockDim.x + threadIdx.x;
    const unsigned* wv = (const unsigned*)batch;
    const bool is64 = (wv[2001] == 0u && wv[4001] == 0u && wv[6001] == 0u && wv[9001] == 0u);
    if (i < N_NODES)
        g_b32[i] = is64 ? (int)((const long long*)batch)[i] : ((const int*)batch)[i];
    if (i < HID * HID) {
        const int k = i >> 8, j = i & 255;        // W1[k][j]
        const __half h = __float2half_rn(W1[i]);
        const int kc = k >> 3;
        const uint32_t off = (uint32_t)(j * 512 + ((kc ^ (j & 7)) << 4) + (k & 7) * 2);
        *(__half*)&g_wimg[off] = h;
    }
}

// ---------------- K1: HMMA GEMM (full N per CTA) + tanh + W2 dot ----------------
// dynamic smem: [W 128K][X stage0 hi16K lo16K][X stage1 hi16K lo16K] = 192K
#define S_W  0
#define S_X  131072
#define SMEM_K1 196608

__global__ void __launch_bounds__(256, 1) k_logits_mma(
    const float* __restrict__ x, const float* __restrict__ b1, const float* __restrict__ W2)
{
    extern __shared__ char sm_[];
    __shared__ float sacc[2][32];
    __shared__ float b1s[256], w2s[256];

    const int tid  = threadIdx.x;
    const int wid  = tid >> 5;
    const int lane = tid & 31;
    const int wm   = wid & 1;     // m half: 16 rows
    const int wn   = wid >> 1;    // n group: 64 units

    // copy W image (128KB)
    {
        const uint4* gw = (const uint4*)&g_wimg[0];
        uint4* dw = (uint4*)(sm_ + S_W);
        for (int i2 = tid; i2 < 8192; i2 += 256) dw[i2] = gw[i2];
    }
    b1s[tid] = b1[tid];
    w2s[tid] = W2[tid];
    if (tid < 32) { sacc[0][tid] = 0.f; sacc[1][tid] = 0.f; }

    const uint32_t sb = smem_u32(sm_);
    const uint32_t wbase = sb + S_W;

    // per-thread load-chunk constants: 8 float4 per thread per 32-node tile
    int rowc[8], qc[8];
    #pragma unroll
    for (int i2 = 0; i2 < 8; i2++) {
        const int c = i2 * 256 + tid;   // float4 index in [0,2048)
        rowc[i2] = c >> 6;              // node row 0..31
        qc[i2]   = c & 63;              // float4 within row
    }

    // ldmatrix lane addressing (layouts proven in round 3/4)
    const int rowA = wm * 16 + (lane & 15);
    const uint32_t aoff = rowA * 512; const int a7 = rowA & 7;
    const int acs = (lane >> 4) & 1;

    uint32_t boffs[4]; int b7s[4];
    #pragma unroll
    for (int g = 0; g < 4; g++) {
        const int rowB = wn * 64 + g * 16 + (lane & 7) + (((lane >> 4) & 1) << 3);
        boffs[g] = wbase + rowB * 512;
        b7s[g]   = rowB & 7;
    }
    const int bcs = (lane >> 3) & 1;

    const int step = (int)gridDim.x;
    const int qid = lane & 3;
    const int rq  = lane >> 2;

    // ---- prologue ----
    float4 pf[8];
    int t = blockIdx.x;
    {   // LDG tile t -> convert -> X stage0
        #pragma unroll
        for (int i2 = 0; i2 < 8; i2++)
            pf[i2] = __ldg((const float4*)(x + (size_t)(t * 32 + rowc[i2]) * HID + qc[i2] * 4));
        #pragma unroll
        for (int i2 = 0; i2 < 8; i2++) {
            const float4 f = pf[i2];
            __half2 h01 = __floats2half2_rn(f.x, f.y);
            __half2 h23 = __floats2half2_rn(f.z, f.w);
            float2 g01 = __half22float2(h01);
            float2 g23 = __half22float2(h23);
            __half2 l01 = __floats2half2_rn(f.x - g01.x, f.y - g01.y);
            __half2 l23 = __floats2half2_rn(f.z - g23.x, f.w - g23.y);
            const uint32_t ad = (uint32_t)(rowc[i2] * 512 + (((qc[i2] >> 1) ^ (rowc[i2] & 7)) << 4) + (qc[i2] & 1) * 8);
            *(uint2*)(sm_ + S_X + ad)          = make_uint2(*(uint32_t*)&h01, *(uint32_t*)&h23);
            *(uint2*)(sm_ + S_X + 16384 + ad)  = make_uint2(*(uint32_t*)&l01, *(uint32_t*)&l23);
        }
        const int tn = t + step;
        if (tn < NTILES) {
            #pragma unroll
            for (int i2 = 0; i2 < 8; i2++)
                pf[i2] = __ldg((const float4*)(x + (size_t)(tn * 32 + rowc[i2]) * HID + qc[i2] * 4));
        }
    }
    __syncthreads();

    int cb = 0;
    for (; t < NTILES; t += step, cb ^= 1) {
        // ---- STS next tile into stage cb^1 ----
        if (t + step < NTILES) {
            char* xb = sm_ + S_X + (cb ^ 1) * 32768;
            #pragma unroll
            for (int i2 = 0; i2 < 8; i2++) {
                const float4 f = pf[i2];
                __half2 h01 = __floats2half2_rn(f.x, f.y);
                __half2 h23 = __floats2half2_rn(f.z, f.w);
                float2 g01 = __half22float2(h01);
                float2 g23 = __half22float2(h23);
                __half2 l01 = __floats2half2_rn(f.x - g01.x, f.y - g01.y);
                __half2 l23 = __floats2half2_rn(f.z - g23.x, f.w - g23.y);
                const uint32_t ad = (uint32_t)(rowc[i2] * 512 + (((qc[i2] >> 1) ^ (rowc[i2] & 7)) << 4) + (qc[i2] & 1) * 8);
                *(uint2*)(xb + ad)         = make_uint2(*(uint32_t*)&h01, *(uint32_t*)&h23);
                *(uint2*)(xb + 16384 + ad) = make_uint2(*(uint32_t*)&l01, *(uint32_t*)&l23);
            }
        }
        // ---- LDG tile t+2*step ----
        {
            const int tn = t + 2 * step;
            if (tn < NTILES) {
                #pragma unroll
                for (int i2 = 0; i2 < 8; i2++)
                    pf[i2] = __ldg((const float4*)(x + (size_t)(tn * 32 + rowc[i2]) * HID + qc[i2] * 4));
            }
        }

        // ---- GEMM on stage cb: D = (Xh + Xl) * Wh ----
        const uint32_t xh = sb + S_X + cb * 32768;
        const uint32_t xl = xh + 16384;

        float d[8][4];
        #pragma unroll
        for (int u = 0; u < 8; u++)
            #pragma unroll
            for (int q = 0; q < 4; q++) d[u][q] = 0.f;

        #pragma unroll 4
        for (int ks = 0; ks < 16; ks++) {
            const uint32_t ao = aoff + ((((ks << 1) + acs) ^ a7) << 4);
            uint32_t Ah[4], Al[4];
            LDSM4(Ah, xh + ao);
            LDSM4(Al, xl + ao);
            #pragma unroll
            for (int g = 0; g < 4; g++) {
                uint32_t B[4];
                LDSM4(B, boffs[g] + ((((ks << 1) + bcs) ^ b7s[g]) << 4));
                MMA16816(d[g * 2 + 0], Ah, B[0], B[1]);
                MMA16816(d[g * 2 + 1], Ah, B[2], B[3]);
                MMA16816(d[g * 2 + 0], Al, B[0], B[1]);
                MMA16816(d[g * 2 + 1], Al, B[2], B[3]);
            }
        }

        // ---- epilogue: tanh(+b1) dot W2 ----
        float s0 = 0.f, s1 = 0.f;
        #pragma unroll
        for (int u = 0; u < 8; u++) {
            const int c0 = wn * 64 + u * 8 + qid * 2;
            const float bb0 = b1s[c0], bb1 = b1s[c0 + 1];
            const float ww0 = w2s[c0], ww1 = w2s[c0 + 1];
            s0 += tanhf(d[u][0] + bb0) * ww0 + tanhf(d[u][1] + bb1) * ww1;
            s1 += tanhf(d[u][2] + bb0) * ww0 + tanhf(d[u][3] + bb1) * ww1;
        }
        s0 += __shfl_xor_sync(0xffffffffu, s0, 1);
        s0 += __shfl_xor_sync(0xffffffffu, s0, 2);
        s1 += __shfl_xor_sync(0xffffffffu, s1, 1);
        s1 += __shfl_xor_sync(0xffffffffu, s1, 2);
        if (qid == 0) {
            atomicAdd(&sacc[cb][wm * 16 + rq], s0);
            atomicAdd(&sacc[cb][wm * 16 + 8 + rq], s1);
        }
        __syncthreads();
        if (tid < 32) {
            g_e[t * 32 + tid] = sacc[cb][tid];
            sacc[cb][tid] = 0.f;
        }
    }
}

// ---------------- k_seg: per-graph softmax + pooling ----------------
__global__ void __launch_bounds__(256) k_seg(const float* __restrict__ x,
                                             float* __restrict__ out)
{
    const int g   = blockIdx.x;
    const int tid = threadIdx.x;
    __shared__ float red[8];
    __shared__ float s_bcast;

    int lo = 0, hi = N_NODES;
    while (lo < hi) { int mid = (lo + hi) >> 1; if (g_b32[mid] < g) lo = mid + 1; else hi = mid; }
    const int beg = lo;
    lo = beg; hi = N_NODES;
    while (lo < hi) { int mid = (lo + hi) >> 1; if (g_b32[mid] < g + 1) lo = mid + 1; else hi = mid; }
    const int end = lo;

    if (end <= beg) { out[(size_t)g * HID + tid] = 0.0f; return; }

    // max
    float m = -1e30f;
    for (int n = beg + tid; n < end; n += 256) m = fmaxf(m, g_e[n]);
    #pragma unroll
    for (int o = 16; o >= 1; o >>= 1) m = fmaxf(m, __shfl_xor_sync(0xffffffffu, m, o));
    if ((tid & 31) == 0) red[tid >> 5] = m;
    __syncthreads();
    if (tid < 8) {
        m = red[tid];
        #pragma unroll
        for (int o = 4; o >= 1; o >>= 1) m = fmaxf(m, __shfl_xor_sync(0xffu, m, o));
        if (tid == 0) s_bcast = m;
    }
    __syncthreads();
    const float mx = s_bcast;
    __syncthreads();

    // exp + sum
    float s = 0.f;
    for (int n = beg + tid; n < end; n += 256) {
        const float e = expf(g_e[n] - mx);
        g_e[n] = e;
        s += e;
    }
    #pragma unroll
    for (int o = 16; o >= 1; o >>= 1) s += __shfl_xor_sync(0xffffffffu, s, o);
    if ((tid & 31) == 0) red[tid >> 5] = s;
    __syncthreads();
    if (tid < 8) {
        s = red[tid];
        #pragma unroll
        for (int o = 4; o >= 1; o >>= 1) s += __shfl_xor_sync(0xffu, s, o);
        if (tid == 0) s_bcast = s;
    }
    __syncthreads();
    const float inv = 1.0f / s_bcast;

    // pooling
    float a0 = 0.f, a1 = 0.f, a2 = 0.f, a3 = 0.f;
    int n = beg;
    for (; n + 3 < end; n += 4) {
        a0 += g_e[n + 0] * x[(size_t)(n + 0) * HID + tid];
        a1 += g_e[n + 1] * x[(size_t)(n + 1) * HID + tid];
        a2 += g_e[n + 2] * x[(size_t)(n + 2) * HID + tid];
        a3 += g_e[n + 3] * x[(size_t)(n + 3) * HID + tid];
    }
    for (; n < end; n++) a0 += g_e[n] * x[(size_t)n * HID + tid];
    out[(size_t)g * HID + tid] = (a0 + a1 + a2 + a3) * inv;
}

// ---------------- launcher ----------------
extern "C" void kernel_launch(void* const* d_in, const int* in_sizes, int n_in,
                              void* d_out, int out_size)
{
    const float* x = nullptr; const void* batch = nullptr;
    const float *W1 = nullptr, *b1 = nullptr, *W2 = nullptr;

    int i = 0;
    for (; i < n_in; i++) if (in_sizes[i] == N_NODES * HID) { x = (const float*)d_in[i]; i++; break; }
    for (; i < n_in; i++) if (in_sizes[i] == N_NODES)       { batch = d_in[i]; i++; break; }
    for (; i < n_in; i++) if (in_sizes[i] == HID * HID)     { W1 = (const float*)d_in[i]; i++; break; }
    for (; i < n_in; i++) if (in_sizes[i] == HID)           { b1 = (const float*)d_in[i]; i++; break; }
    for (; i < n_in; i++) if (in_sizes[i] == HID)           { W2 = (const float*)d_in[i]; i++; break; }
    // b2 dropped: softmax is shift-invariant
    if (!x || !batch || !W1 || !b1 || !W2) return;

    float* out = (float*)d_out;

    static int nsm = 0;
    if (nsm == 0) {
        if (cudaDeviceGetAttribute(&nsm, cudaDevAttrMultiProcessorCount, 0) != cudaSuccess || nsm <= 0)
            nsm = 148;
    }

    cudaFuncSetAttribute(k_logits_mma, cudaFuncAttributeMaxDynamicSharedMemorySize, SMEM_K1);

    // launch slots 1,2 = nops so the profiler's fixed 4th-launch capture lands on k_logits_mma
    k_nop<<<1, 1>>>();
    k_nop<<<1, 1>>>();
    k_prep<<<(N_NODES + 255) / 256, 256>>>(W1, batch);
    k_logits_mma<<<nsm, 256, SMEM_K1>>>(x, b1, W2);
    k_seg<<<NGRAPH, 256>>>(x, out);
}